// round 15
// baseline (speedup 1.0000x reference)
#include <cuda_runtime.h>
#include <math_constants.h>

#define NQ    4096
#define NKV   4096
#define FDIM  256
#define NH    8
#define HD    32
#define R2    9.0f
#define SCALE 0.17677669529663687f  // 1/sqrt(32)

#define NCELL   4096      // 16^3 cells of size 1.0
#define NSC     64        // 4^3 supercells
#define QBLK    32        // queries per attention block (supercell-pure)
#define BLKS_PER_SC 5     // capacity 160 queries/supercell (Poisson(64) safe)
#define NBLK    (NSC * BLKS_PER_SC)   // 320

// Scratch (device globals: no allocation allowed in kernel_launch)
__device__ float g_Q[NQ * FDIM];
__device__ float g_K[NKV * FDIM];
__device__ float g_V[NKV * FDIM];
__device__ float g_att[NQ * FDIM];

__device__ int g_qstart[NCELL + 1];
__device__ int g_qperm[NQ];
__device__ int g_cand[NBLK * NKV];
__device__ int g_ncand[NBLK];
__device__ int g_border[NBLK];

// ---------------------------------------------------------------------------
// Morton cell id (4 bits/axis, 16x16x16)
// ---------------------------------------------------------------------------
__device__ __forceinline__ int cell_of(float x, float y, float z)
{
    int cx = min(15, max(0, (int)x));
    int cy = min(15, max(0, (int)y));
    int cz = min(15, max(0, (int)z));
    int m = 0;
    #pragma unroll
    for (int i = 0; i < 4; i++) {
        m |= ((cx >> i) & 1) << (3 * i);
        m |= ((cy >> i) & 1) << (3 * i + 1);
        m |= ((cz >> i) & 1) << (3 * i + 2);
    }
    return m;
}

// ---------------------------------------------------------------------------
// Fused setup: histogram + exclusive scan + scatter, one block, all in smem.
// ---------------------------------------------------------------------------
__global__ __launch_bounds__(1024)
void setup_kernel(const float* __restrict__ cc)
{
    __shared__ int hist[NCELL];
    __shared__ int start[NCELL];
    __shared__ int wsum[32];
    const int tid = threadIdx.x;

    for (int i = tid; i < NCELL; i += 1024) hist[i] = 0;
    __syncthreads();

    int mycell[4];
    #pragma unroll
    for (int j = 0; j < 4; j++) {
        int q = tid + j * 1024;
        int c = cell_of(cc[3 * q], cc[3 * q + 1], cc[3 * q + 2]);
        mycell[j] = c;
        atomicAdd(&hist[c], 1);
    }
    __syncthreads();

    // exclusive scan of 4096 (4 per thread)
    int v0 = hist[4 * tid + 0], v1 = hist[4 * tid + 1];
    int v2 = hist[4 * tid + 2], v3 = hist[4 * tid + 3];
    int s = v0 + v1 + v2 + v3;
    int lane = tid & 31, wid = tid >> 5;
    int inc = s;
    #pragma unroll
    for (int o = 1; o < 32; o <<= 1) {
        int n = __shfl_up_sync(0xffffffffu, inc, o);
        if (lane >= o) inc += n;
    }
    if (lane == 31) wsum[wid] = inc;
    __syncthreads();
    if (wid == 0) {
        int w = wsum[lane];
        #pragma unroll
        for (int o = 1; o < 32; o <<= 1) {
            int n = __shfl_up_sync(0xffffffffu, w, o);
            if (lane >= o) w += n;
        }
        wsum[lane] = w;
    }
    __syncthreads();
    int excl = inc - s + (wid > 0 ? wsum[wid - 1] : 0);
    start[4 * tid + 0] = excl;
    start[4 * tid + 1] = excl + v0;
    start[4 * tid + 2] = excl + v0 + v1;
    start[4 * tid + 3] = excl + v0 + v1 + v2;
    g_qstart[4 * tid + 0] = excl;
    g_qstart[4 * tid + 1] = excl + v0;
    g_qstart[4 * tid + 2] = excl + v0 + v1;
    g_qstart[4 * tid + 3] = excl + v0 + v1 + v2;
    if (tid == 1023) g_qstart[NCELL] = excl + s;
    __syncthreads();

    // scatter (start[] doubles as running counters)
    #pragma unroll
    for (int j = 0; j < 4; j++) {
        int q = tid + j * 1024;
        int pos = atomicAdd(&start[mycell[j]], 1);
        g_qperm[pos] = q;
    }
}

// ---------------------------------------------------------------------------
// Candidate keys per 32-query supercell-pure chunk: keys with
// dist(key, chunk-bbox) <= R. Deterministic compaction.
// ---------------------------------------------------------------------------
__global__ __launch_bounds__(256)
void cand_kernel(const float* __restrict__ cc, const float* __restrict__ hc)
{
    const int b = blockIdx.x;
    const int sc = b / BLKS_PER_SC;
    const int j  = b - sc * BLKS_PER_SC;
    const int base = sc << 6;
    const int s0 = g_qstart[base];
    const int s1 = g_qstart[base + 64];
    const int qs = s0 + QBLK * j;
    const int cnt = min(QBLK, s1 - qs);
    const int tid = threadIdx.x;
    if (cnt <= 0) { if (tid == 0) g_ncand[b] = 0; return; }

    __shared__ float sx[QBLK], sy[QBLK], sz[QBLK];
    __shared__ float blo[3], bhi[3];
    if (tid < QBLK) {
        float x = 1e30f, y = 1e30f, z = 1e30f;
        if (tid < cnt) {
            int q = g_qperm[qs + tid];
            x = cc[3 * q]; y = cc[3 * q + 1]; z = cc[3 * q + 2];
        }
        sx[tid] = x; sy[tid] = y; sz[tid] = z;
    }
    __syncthreads();
    if (tid == 0) {
        float x = 1e30f, y = 1e30f, z = 1e30f, X = -1e30f, Y = -1e30f, Z = -1e30f;
        for (int i = 0; i < cnt; i++) {
            x = fminf(x, sx[i]); y = fminf(y, sy[i]); z = fminf(z, sz[i]);
            X = fmaxf(X, sx[i]); Y = fmaxf(Y, sy[i]); Z = fmaxf(Z, sz[i]);
        }
        blo[0] = x; blo[1] = y; blo[2] = z;
        bhi[0] = X; bhi[1] = Y; bhi[2] = Z;
    }

    __shared__ int wcnt[8];
    __shared__ int total;
    if (tid == 0) total = 0;
    __syncthreads();

    const int lane = tid & 31, wid = tid >> 5;
    const long long boff = (long long)b * NKV;
    for (int t0 = 0; t0 < NKV; t0 += 256) {
        int t = t0 + tid;
        float kx = hc[3 * t], ky = hc[3 * t + 1], kz = hc[3 * t + 2];
        float dx = fmaxf(0.f, fmaxf(blo[0] - kx, kx - bhi[0]));
        float dy = fmaxf(0.f, fmaxf(blo[1] - ky, ky - bhi[1]));
        float dz = fmaxf(0.f, fmaxf(blo[2] - kz, kz - bhi[2]));
        bool pass = (dx * dx + dy * dy + dz * dz) <= (R2 + 1e-3f);
        unsigned m = __ballot_sync(0xffffffffu, pass);
        if (lane == 0) wcnt[wid] = __popc(m);
        __syncthreads();
        int off = 0;
        for (int w = 0; w < wid; w++) off += wcnt[w];
        if (pass)
            g_cand[boff + total + off + __popc(m & ((1u << lane) - 1u))] = t;
        __syncthreads();
        if (tid == 0) {
            int su = 0;
            for (int w = 0; w < 8; w++) su += wcnt[w];
            total += su;
        }
        __syncthreads();
    }
    if (tid == 0) g_ncand[b] = total;
}

// ---------------------------------------------------------------------------
// Rank-sort blocks by candidate count (descending) -> longest-first launch.
// ---------------------------------------------------------------------------
__global__ void order_kernel()
{
    const int t = threadIdx.x;
    if (t >= NBLK) return;
    const int my = g_ncand[t];
    int rank = 0;
    for (int j = 0; j < NBLK; j++) {
        int nj = g_ncand[j];
        if (nj > my || (nj == my && j < t)) rank++;
    }
    g_border[rank] = t;
}

// ---------------------------------------------------------------------------
// GEMM (NT + bias): C[M,256] = A[M,256] @ W[256,256]^T + bias
// 128x64 block tile, BK=32, 128 threads, 8x8 microtile:
// 4 LDS.128 per 64 FMA (16:1) -> FMA-bound, not L1-bound.
// Smem transposed [k][row] with XOR swizzle row' = row ^ (k & 28); the
// 8-row-group read uses the two-float4 pattern proven in the 8x4 variant.
// ---------------------------------------------------------------------------
__device__ __forceinline__ void gemm_body(
    const float* __restrict__ A, const float* __restrict__ W,
    const float* __restrict__ bias, float* __restrict__ C)
{
    __shared__ float Ash[32][128];
    __shared__ float Bsh[32][64];

    const int tid = threadIdx.x;
    const int tx = tid & 7;         // 8 col groups (8 cols each)
    const int ty = tid >> 3;        // 16 row groups (8 rows each)
    const int row0 = blockIdx.x * 128;
    const int col0 = blockIdx.y * 64;

    float acc[8][8] = {};

    for (int k0 = 0; k0 < FDIM; k0 += 32) {
        // A tile: 128 rows x 8 quads = 1024 float4 slots over 128 threads
        #pragma unroll
        for (int i = 0; i < 8; i++) {
            int idx = tid + i * 128;
            int r   = idx >> 3;
            int c4  = idx & 7;
            float4 va = *(const float4*)(A + (size_t)(row0 + r) * FDIM + k0 + c4 * 4);
            int rs = r ^ (c4 * 4);
            Ash[c4 * 4 + 0][rs] = va.x; Ash[c4 * 4 + 1][rs] = va.y;
            Ash[c4 * 4 + 2][rs] = va.z; Ash[c4 * 4 + 3][rs] = va.w;
        }
        // B tile: 64 rows x 8 quads = 512 float4 slots
        #pragma unroll
        for (int i = 0; i < 4; i++) {
            int idx = tid + i * 128;
            int r   = idx >> 3;
            int c4  = idx & 7;
            float4 vb = *(const float4*)(W + (size_t)(col0 + r) * FDIM + k0 + c4 * 4);
            int rs = r ^ (c4 * 4);
            Bsh[c4 * 4 + 0][rs] = vb.x; Bsh[c4 * 4 + 1][rs] = vb.y;
            Bsh[c4 * 4 + 2][rs] = vb.z; Bsh[c4 * 4 + 3][rs] = vb.w;
        }
        __syncthreads();

        #pragma unroll
        for (int kk = 0; kk < 32; kk++) {
            const int s = kk & 28;
            // 8-row group under XOR swizzle: a[0..3] = rows +0..3,
            // a[4..7] = rows +4..7 (two float4s, halves swapped by s&4)
            const int ab = (ty * 8) ^ (s & 24);
            float4 a0 = *(const float4*)&Ash[kk][ab + (s & 4)];
            float4 a1 = *(const float4*)&Ash[kk][ab + (4 ^ (s & 4))];
            const int bbse = (tx * 8) ^ (s & 24);
            float4 b0 = *(const float4*)&Bsh[kk][bbse + (s & 4)];
            float4 b1 = *(const float4*)&Bsh[kk][bbse + (4 ^ (s & 4))];
            float a[8] = {a0.x, a0.y, a0.z, a0.w, a1.x, a1.y, a1.z, a1.w};
            float b[8] = {b0.x, b0.y, b0.z, b0.w, b1.x, b1.y, b1.z, b1.w};
            #pragma unroll
            for (int i = 0; i < 8; i++)
                #pragma unroll
                for (int j = 0; j < 8; j++)
                    acc[i][j] += a[i] * b[j];
        }
        __syncthreads();
    }

    float4 bb0 = *(const float4*)(bias + col0 + tx * 8);
    float4 bb1 = *(const float4*)(bias + col0 + tx * 8 + 4);
    #pragma unroll
    for (int i = 0; i < 8; i++) {
        float* Cp = C + (size_t)(row0 + ty * 8 + i) * FDIM + col0 + tx * 8;
        float4 o0, o1;
        o0.x = acc[i][0] + bb0.x; o0.y = acc[i][1] + bb0.y;
        o0.z = acc[i][2] + bb0.z; o0.w = acc[i][3] + bb0.w;
        o1.x = acc[i][4] + bb1.x; o1.y = acc[i][5] + bb1.y;
        o1.z = acc[i][6] + bb1.z; o1.w = acc[i][7] + bb1.w;
        *(float4*)Cp       = o0;
        *(float4*)(Cp + 4) = o1;
    }
}

__global__ __launch_bounds__(128, 4)
void qkv_gemm(const float* __restrict__ cur, const float* __restrict__ hist,
              const float* __restrict__ Wq, const float* __restrict__ bq,
              const float* __restrict__ Wk, const float* __restrict__ bk,
              const float* __restrict__ Wv, const float* __restrict__ bv)
{
    const float* A; const float* W; const float* bias; float* C;
    if (blockIdx.z == 0)      { A = cur;  W = Wq; bias = bq; C = g_Q; }
    else if (blockIdx.z == 1) { A = hist; W = Wk; bias = bk; C = g_K; }
    else                      { A = hist; W = Wv; bias = bv; C = g_V; }
    gemm_body(A, W, bias, C);
}

__global__ __launch_bounds__(128, 4)
void out_gemm(const float* __restrict__ Wo, const float* __restrict__ bo,
              float* __restrict__ out)
{
    gemm_body(g_att, Wo, bo, out);
}

// ---------------------------------------------------------------------------
// Masked flash attention over supercell-pure 32-query chunks.
// (unchanged from the 180.4us round-14 winner)
// ---------------------------------------------------------------------------
__global__ __launch_bounds__(128, 6)
void attn_kernel(const float* __restrict__ cc, const float* __restrict__ hc)
{
    const int b  = g_border[blockIdx.x];
    const int sc = b / BLKS_PER_SC;
    const int j  = b - sc * BLKS_PER_SC;
    const int base = sc << 6;
    const int qs  = g_qstart[base] + QBLK * j;
    const int cnt = min(QBLK, g_qstart[base + 64] - qs);
    if (cnt <= 0) return;

    __shared__ float Qsh[HD][QBLK];     // [d][query], swizzled
    __shared__ float Ksh[HD][64];       // [d][key], swizzled
    __shared__ float Vsh[64][HD];       // [key][d]
    __shared__ float Ssh[64][QBLK];     // p transposed [key][query], swizzled
    __shared__ float qcx[QBLK], qcy[QBLK], qcz[QBLK];
    __shared__ float kcx[64], kcy[64], kcz[64];
    __shared__ float lsh[QBLK];

    const int tid = threadIdx.x;
    const int h   = blockIdx.y;
    // scores mapping: 8 q-groups x 16 k-groups
    const int ty = tid >> 4, tx = tid & 15;
    // PV mapping: 8 q-groups x 8 d-groups x 2 key-halves
    const int qg = tid & 7, dg = (tid >> 3) & 7, half = tid >> 6;

    // Load Q tile (transposed+swizzled): 32 rows x 8 quads = 256 slots
    #pragma unroll
    for (int i = 0; i < 2; i++) {
        int idx = tid + i * 128;
        int r   = idx >> 3;          // query row 0..31
        int c4  = idx & 7;           // dim quad 0..7
        int qv  = (r < cnt) ? g_qperm[qs + r] : g_qperm[qs];
        float4 v = *(const float4*)(g_Q + (size_t)qv * FDIM + h * HD + c4 * 4);
        int rs = r ^ (c4 * 4);
        Qsh[c4 * 4 + 0][rs] = v.x; Qsh[c4 * 4 + 1][rs] = v.y;
        Qsh[c4 * 4 + 2][rs] = v.z; Qsh[c4 * 4 + 3][rs] = v.w;
    }
    if (tid < QBLK) {
        if (tid < cnt) {
            int qv = g_qperm[qs + tid];
            qcx[tid] = cc[3 * qv]; qcy[tid] = cc[3 * qv + 1]; qcz[tid] = cc[3 * qv + 2];
        } else {
            qcx[tid] = -1e9f; qcy[tid] = -1e9f; qcz[tid] = -1e9f;
        }
    }
    __syncthreads();

    // query coords for this thread's 4 score-rows (block-constant)
    float qx[4], qy[4], qz[4];
    #pragma unroll
    for (int i = 0; i < 4; i++) {
        qx[i] = qcx[ty * 4 + i]; qy[i] = qcy[ty * 4 + i]; qz[i] = qcz[ty * 4 + i];
    }

    const int nc = g_ncand[b];
    const long long boff = (long long)b * NKV;

    float l[4] = {0.f, 0.f, 0.f, 0.f};
    float o[4][4] = {};

    for (int t0 = 0; t0 < nc; t0 += 64) {
        __syncthreads();   // prior PV reads done before overwrite
        // K/V gather: 64 rows x 8 quads = 512 slots over 128 threads
        #pragma unroll
        for (int i = 0; i < 4; i++) {
            int idx = tid + i * 128;
            int r   = idx >> 3;
            int c4  = idx & 7;
            int t   = t0 + r;
            int ci  = (t < nc) ? g_cand[boff + t] : 0;
            float4 kv = *(const float4*)(g_K + (size_t)ci * FDIM + h * HD + c4 * 4);
            int rs = r ^ (c4 * 4);
            Ksh[c4 * 4 + 0][rs] = kv.x; Ksh[c4 * 4 + 1][rs] = kv.y;
            Ksh[c4 * 4 + 2][rs] = kv.z; Ksh[c4 * 4 + 3][rs] = kv.w;
            float4 vv = *(const float4*)(g_V + (size_t)ci * FDIM + h * HD + c4 * 4);
            *(float4*)&Vsh[r][c4 * 4] = vv;
        }
        if (tid < 64) {
            int t = t0 + tid;
            if (t < nc) {
                int ci = g_cand[boff + t];
                kcx[tid] = hc[3 * ci + 0];
                kcy[tid] = hc[3 * ci + 1];
                kcz[tid] = hc[3 * ci + 2];
            } else {
                kcx[tid] = 1e9f; kcy[tid] = 1e9f; kcz[tid] = 1e9f;
            }
        }
        __syncthreads();

        // ---- scores: 4q x 4k microtile ----
        float s[4][4] = {};
        #pragma unroll
        for (int d = 0; d < HD; d++) {
            const int sw = d & 28;
            float4 q4 = *(const float4*)&Qsh[d][(ty * 4) ^ sw];
            float4 k4 = *(const float4*)&Ksh[d][(tx * 4) ^ sw];
            float qa[4] = {q4.x, q4.y, q4.z, q4.w};
            float ka[4] = {k4.x, k4.y, k4.z, k4.w};
            #pragma unroll
            for (int i = 0; i < 4; i++)
                #pragma unroll
                for (int jj = 0; jj < 4; jj++)
                    s[i][jj] += qa[i] * ka[jj];
        }

        float kx[4], ky[4], kz[4];
        #pragma unroll
        for (int jj = 0; jj < 4; jj++) {
            kx[jj] = kcx[tx * 4 + jj]; ky[jj] = kcy[tx * 4 + jj]; kz[jj] = kcz[tx * 4 + jj];
        }

        // ---- mask + exp (static base), accumulate partial l ----
        #pragma unroll
        for (int i = 0; i < 4; i++) {
            #pragma unroll
            for (int jj = 0; jj < 4; jj++) {
                float dx = qx[i] - kx[jj], dy = qy[i] - ky[jj], dz = qz[i] - kz[jj];
                float d2 = dx * dx + dy * dy + dz * dz;
                float p = (d2 <= R2) ? __expf(s[i][jj] * SCALE) : 0.f;
                s[i][jj] = p;
                l[i] += p;
            }
        }

        // store p transposed+swizzled: Ssh[k][(ty ^ ((k>>2)&7))*4 ..]
        #pragma unroll
        for (int jj = 0; jj < 4; jj++) {
            int k = tx * 4 + jj;
            float4 pv = {s[0][jj], s[1][jj], s[2][jj], s[3][jj]};
            *(float4*)&Ssh[k][(ty ^ (tx & 7)) * 4] = pv;
        }
        __syncthreads();

        // ---- PV: 4q x 4d over this thread's 32-key half ----
        const int kbase = half * 32;
        #pragma unroll 8
        for (int kk = 0; kk < 32; kk++) {
            int k = kbase + kk;
            float4 p4 = *(const float4*)&Ssh[k][(qg ^ ((k >> 2) & 7)) * 4];
            float4 v4 = *(const float4*)&Vsh[k][dg * 4];
            o[0][0] += p4.x * v4.x; o[0][1] += p4.x * v4.y; o[0][2] += p4.x * v4.z; o[0][3] += p4.x * v4.w;
            o[1][0] += p4.y * v4.x; o[1][1] += p4.y * v4.y; o[1][2] += p4.y * v4.z; o[1][3] += p4.y * v4.w;
            o[2][0] += p4.z * v4.x; o[2][1] += p4.z * v4.y; o[2][2] += p4.z * v4.z; o[2][3] += p4.z * v4.w;
            o[3][0] += p4.w * v4.x; o[3][1] += p4.w * v4.y; o[3][2] += p4.w * v4.z; o[3][3] += p4.w * v4.w;
        }
    }

    // ---- final l reduction over the 16 tx lanes (once) ----
    #pragma unroll
    for (int i = 0; i < 4; i++) {
        float ls = l[i];
        ls += __shfl_xor_sync(0xffffffffu, ls, 1);
        ls += __shfl_xor_sync(0xffffffffu, ls, 2);
        ls += __shfl_xor_sync(0xffffffffu, ls, 4);
        ls += __shfl_xor_sync(0xffffffffu, ls, 8);
        l[i] = ls;
    }
    if (tx == 0) {
        lsh[ty * 4 + 0] = l[0]; lsh[ty * 4 + 1] = l[1];
        lsh[ty * 4 + 2] = l[2]; lsh[ty * 4 + 3] = l[3];
    }
    __syncthreads();

    // ---- finalize: merge halves, divide by l (l==0 -> NaN like reference) ----
    if (half == 1) {
        #pragma unroll
        for (int i = 0; i < 4; i++) {
            float4 w = {o[i][0], o[i][1], o[i][2], o[i][3]};
            *(float4*)&Ssh[qg * 4 + i][dg * 4] = w;
        }
    }
    __syncthreads();
    if (half == 0) {
        #pragma unroll
        for (int i = 0; i < 4; i++) {
            int qrel = qg * 4 + i;
            if (qrel < cnt) {
                float inv = 1.f / lsh[qrel];
                float4 ot = *(const float4*)&Ssh[qrel][dg * 4];
                int qv = g_qperm[qs + qrel];
                float4 r;
                r.x = (o[i][0] + ot.x) * inv;
                r.y = (o[i][1] + ot.y) * inv;
                r.z = (o[i][2] + ot.z) * inv;
                r.w = (o[i][3] + ot.w) * inv;
                *(float4*)(g_att + (size_t)qv * FDIM + h * HD + dg * 4) = r;
            }
        }
    }
}

// ---------------------------------------------------------------------------
extern "C" void kernel_launch(void* const* d_in, const int* in_sizes, int n_in,
                              void* d_out, int out_size)
{
    const float* cur  = (const float*)d_in[0];
    const float* hist = (const float*)d_in[1];
    const float* cc   = (const float*)d_in[2];
    const float* hc   = (const float*)d_in[3];
    const float* Wq   = (const float*)d_in[4];
    const float* bq   = (const float*)d_in[5];
    const float* Wk   = (const float*)d_in[6];
    const float* bk   = (const float*)d_in[7];
    const float* Wv   = (const float*)d_in[8];
    const float* bv   = (const float*)d_in[9];
    const float* Wo   = (const float*)d_in[10];
    const float* bo   = (const float*)d_in[11];
    float* out = (float*)d_out;

    setup_kernel<<<1, 1024>>>(cc);
    cand_kernel<<<NBLK, 256>>>(cc, hc);
    order_kernel<<<1, NBLK>>>();

    dim3 g1(NQ / 128, FDIM / 64, 3);
    qkv_gemm<<<g1, 128>>>(cur, hist, Wq, bq, Wk, bk, Wv, bv);

    dim3 g2(NBLK, NH);
    attn_kernel<<<g2, 128>>>(cc, hc);

    dim3 g3(NQ / 128, FDIM / 64);
    out_gemm<<<g3, 128>>>(Wo, bo, out);
}

// round 17
// speedup vs baseline: 1.1627x; 1.1627x over previous
#include <cuda_runtime.h>
#include <math_constants.h>

#define NQ    4096
#define NKV   4096
#define FDIM  256
#define NH    8
#define HD    32
#define R2    9.0f
#define SCALE 0.17677669529663687f  // 1/sqrt(32)

#define NCELL   4096      // 16^3 cells of size 1.0
#define NSC     64        // 4^3 supercells
#define QBLK    32        // queries per attention block (supercell-pure)
#define BLKS_PER_SC 5     // capacity 160 queries/supercell (Poisson(64) safe)
#define NBLK    (NSC * BLKS_PER_SC)   // 320

// Scratch (device globals: no allocation allowed in kernel_launch)
__device__ float g_Q[NQ * FDIM];
__device__ float g_K[NKV * FDIM];
__device__ float g_V[NKV * FDIM];
__device__ float g_att[NQ * FDIM];

__device__ int g_qstart[NCELL + 1];
__device__ int g_qperm[NQ];
__device__ int g_cand[NBLK * NKV];
__device__ int g_ncand[NBLK];
__device__ int g_border[NBLK];

// ---------------------------------------------------------------------------
// Morton cell id (4 bits/axis, 16x16x16)
// ---------------------------------------------------------------------------
__device__ __forceinline__ int cell_of(float x, float y, float z)
{
    int cx = min(15, max(0, (int)x));
    int cy = min(15, max(0, (int)y));
    int cz = min(15, max(0, (int)z));
    int m = 0;
    #pragma unroll
    for (int i = 0; i < 4; i++) {
        m |= ((cx >> i) & 1) << (3 * i);
        m |= ((cy >> i) & 1) << (3 * i + 1);
        m |= ((cz >> i) & 1) << (3 * i + 2);
    }
    return m;
}

// ---------------------------------------------------------------------------
// Fused setup: histogram + exclusive scan + scatter, one block, all in smem.
// ---------------------------------------------------------------------------
__global__ __launch_bounds__(1024)
void setup_kernel(const float* __restrict__ cc)
{
    __shared__ int hist[NCELL];
    __shared__ int start[NCELL];
    __shared__ int wsum[32];
    const int tid = threadIdx.x;

    for (int i = tid; i < NCELL; i += 1024) hist[i] = 0;
    __syncthreads();

    int mycell[4];
    #pragma unroll
    for (int j = 0; j < 4; j++) {
        int q = tid + j * 1024;
        int c = cell_of(cc[3 * q], cc[3 * q + 1], cc[3 * q + 2]);
        mycell[j] = c;
        atomicAdd(&hist[c], 1);
    }
    __syncthreads();

    // exclusive scan of 4096 (4 per thread)
    int v0 = hist[4 * tid + 0], v1 = hist[4 * tid + 1];
    int v2 = hist[4 * tid + 2], v3 = hist[4 * tid + 3];
    int s = v0 + v1 + v2 + v3;
    int lane = tid & 31, wid = tid >> 5;
    int inc = s;
    #pragma unroll
    for (int o = 1; o < 32; o <<= 1) {
        int n = __shfl_up_sync(0xffffffffu, inc, o);
        if (lane >= o) inc += n;
    }
    if (lane == 31) wsum[wid] = inc;
    __syncthreads();
    if (wid == 0) {
        int w = wsum[lane];
        #pragma unroll
        for (int o = 1; o < 32; o <<= 1) {
            int n = __shfl_up_sync(0xffffffffu, w, o);
            if (lane >= o) w += n;
        }
        wsum[lane] = w;
    }
    __syncthreads();
    int excl = inc - s + (wid > 0 ? wsum[wid - 1] : 0);
    start[4 * tid + 0] = excl;
    start[4 * tid + 1] = excl + v0;
    start[4 * tid + 2] = excl + v0 + v1;
    start[4 * tid + 3] = excl + v0 + v1 + v2;
    g_qstart[4 * tid + 0] = excl;
    g_qstart[4 * tid + 1] = excl + v0;
    g_qstart[4 * tid + 2] = excl + v0 + v1;
    g_qstart[4 * tid + 3] = excl + v0 + v1 + v2;
    if (tid == 1023) g_qstart[NCELL] = excl + s;
    __syncthreads();

    // scatter (start[] doubles as running counters)
    #pragma unroll
    for (int j = 0; j < 4; j++) {
        int q = tid + j * 1024;
        int pos = atomicAdd(&start[mycell[j]], 1);
        g_qperm[pos] = q;
    }
}

// ---------------------------------------------------------------------------
// Candidate keys per 32-query supercell-pure chunk: keys with
// dist(key, chunk-bbox) <= R. Deterministic compaction, 512 threads
// (8 chunks of 512 keys -> half the barrier iterations of the 256t version).
// ---------------------------------------------------------------------------
__global__ __launch_bounds__(512)
void cand_kernel(const float* __restrict__ cc, const float* __restrict__ hc)
{
    const int b = blockIdx.x;
    const int sc = b / BLKS_PER_SC;
    const int j  = b - sc * BLKS_PER_SC;
    const int base = sc << 6;
    const int s0 = g_qstart[base];
    const int s1 = g_qstart[base + 64];
    const int qs = s0 + QBLK * j;
    const int cnt = min(QBLK, s1 - qs);
    const int tid = threadIdx.x;
    if (cnt <= 0) { if (tid == 0) g_ncand[b] = 0; return; }

    __shared__ float sx[QBLK], sy[QBLK], sz[QBLK];
    __shared__ float blo[3], bhi[3];
    if (tid < QBLK) {
        float x = 1e30f, y = 1e30f, z = 1e30f;
        if (tid < cnt) {
            int q = g_qperm[qs + tid];
            x = cc[3 * q]; y = cc[3 * q + 1]; z = cc[3 * q + 2];
        }
        sx[tid] = x; sy[tid] = y; sz[tid] = z;
    }
    __syncthreads();
    if (tid == 0) {
        float x = 1e30f, y = 1e30f, z = 1e30f, X = -1e30f, Y = -1e30f, Z = -1e30f;
        for (int i = 0; i < cnt; i++) {
            x = fminf(x, sx[i]); y = fminf(y, sy[i]); z = fminf(z, sz[i]);
            X = fmaxf(X, sx[i]); Y = fmaxf(Y, sy[i]); Z = fmaxf(Z, sz[i]);
        }
        blo[0] = x; blo[1] = y; blo[2] = z;
        bhi[0] = X; bhi[1] = Y; bhi[2] = Z;
    }

    __shared__ int wcnt[16];
    __shared__ int total;
    if (tid == 0) total = 0;
    __syncthreads();

    const int lane = tid & 31, wid = tid >> 5;
    const long long boff = (long long)b * NKV;
    for (int t0 = 0; t0 < NKV; t0 += 512) {
        int t = t0 + tid;
        float kx = hc[3 * t], ky = hc[3 * t + 1], kz = hc[3 * t + 2];
        float dx = fmaxf(0.f, fmaxf(blo[0] - kx, kx - bhi[0]));
        float dy = fmaxf(0.f, fmaxf(blo[1] - ky, ky - bhi[1]));
        float dz = fmaxf(0.f, fmaxf(blo[2] - kz, kz - bhi[2]));
        bool pass = (dx * dx + dy * dy + dz * dz) <= (R2 + 1e-3f);
        unsigned m = __ballot_sync(0xffffffffu, pass);
        if (lane == 0) wcnt[wid] = __popc(m);
        __syncthreads();
        int off = 0;
        for (int w = 0; w < wid; w++) off += wcnt[w];
        if (pass)
            g_cand[boff + total + off + __popc(m & ((1u << lane) - 1u))] = t;
        __syncthreads();
        if (tid == 0) {
            int su = 0;
            for (int w = 0; w < 16; w++) su += wcnt[w];
            total += su;
        }
        __syncthreads();
    }
    if (tid == 0) g_ncand[b] = total;
}

// ---------------------------------------------------------------------------
// Rank-sort blocks by candidate count (descending) -> longest-first launch.
// ---------------------------------------------------------------------------
__global__ void order_kernel()
{
    const int t = threadIdx.x;
    if (t >= NBLK) return;
    const int my = g_ncand[t];
    int rank = 0;
    for (int j = 0; j < NBLK; j++) {
        int nj = g_ncand[j];
        if (nj > my || (nj == my && j < t)) rank++;
    }
    g_border[rank] = t;
}

// ---------------------------------------------------------------------------
// GEMM (NT + bias): C[M,256] = A[M,256] @ W[256,256]^T + bias
// 64x64 block tile, BK=32, 256 threads, 4x4 microtile, register prefetch
// across k0. (R13/R14 proven version — frozen.)
// ---------------------------------------------------------------------------
__device__ __forceinline__ void gemm_body(
    const float* __restrict__ A, const float* __restrict__ W,
    const float* __restrict__ bias, float* __restrict__ C)
{
    __shared__ float Ash[32][64];
    __shared__ float Bsh[32][64];

    const int tid = threadIdx.x;
    const int tx = tid & 15;
    const int ty = tid >> 4;
    const int row0 = blockIdx.x * 64;
    const int col0 = blockIdx.y * 64;

    const int r0 = tid >> 3,          c4 = tid & 7;
    const int r1 = (tid + 256) >> 3;
    const int rs0 = r0 ^ (c4 * 4);
    const int rs1 = r1 ^ (c4 * 4);
    const float* Ap0 = A + (size_t)(row0 + r0) * FDIM + c4 * 4;
    const float* Ap1 = A + (size_t)(row0 + r1) * FDIM + c4 * 4;
    const float* Wp0 = W + (size_t)(col0 + r0) * FDIM + c4 * 4;
    const float* Wp1 = W + (size_t)(col0 + r1) * FDIM + c4 * 4;

    {
        float4 va0 = *(const float4*)(Ap0);
        float4 va1 = *(const float4*)(Ap1);
        float4 vb0 = *(const float4*)(Wp0);
        float4 vb1 = *(const float4*)(Wp1);
        Ash[c4 * 4 + 0][rs0] = va0.x; Ash[c4 * 4 + 1][rs0] = va0.y;
        Ash[c4 * 4 + 2][rs0] = va0.z; Ash[c4 * 4 + 3][rs0] = va0.w;
        Ash[c4 * 4 + 0][rs1] = va1.x; Ash[c4 * 4 + 1][rs1] = va1.y;
        Ash[c4 * 4 + 2][rs1] = va1.z; Ash[c4 * 4 + 3][rs1] = va1.w;
        Bsh[c4 * 4 + 0][rs0] = vb0.x; Bsh[c4 * 4 + 1][rs0] = vb0.y;
        Bsh[c4 * 4 + 2][rs0] = vb0.z; Bsh[c4 * 4 + 3][rs0] = vb0.w;
        Bsh[c4 * 4 + 0][rs1] = vb1.x; Bsh[c4 * 4 + 1][rs1] = vb1.y;
        Bsh[c4 * 4 + 2][rs1] = vb1.z; Bsh[c4 * 4 + 3][rs1] = vb1.w;
    }
    __syncthreads();

    float acc[4][4] = {};

    for (int k0 = 0; k0 < FDIM; k0 += 32) {
        const bool have = (k0 + 32 < FDIM);
        float4 na0, na1, nb0, nb1;
        if (have) {
            na0 = *(const float4*)(Ap0 + k0 + 32);
            na1 = *(const float4*)(Ap1 + k0 + 32);
            nb0 = *(const float4*)(Wp0 + k0 + 32);
            nb1 = *(const float4*)(Wp1 + k0 + 32);
        }

        #pragma unroll
        for (int kk = 0; kk < 32; kk++) {
            const int s = kk & 28;
            float4 a4 = *(const float4*)&Ash[kk][(ty * 4) ^ s];
            float4 b4 = *(const float4*)&Bsh[kk][(tx * 4) ^ s];
            float a[4] = {a4.x, a4.y, a4.z, a4.w};
            float b[4] = {b4.x, b4.y, b4.z, b4.w};
            #pragma unroll
            for (int i = 0; i < 4; i++)
                #pragma unroll
                for (int j = 0; j < 4; j++)
                    acc[i][j] += a[i] * b[j];
        }

        if (have) {
            __syncthreads();
            Ash[c4 * 4 + 0][rs0] = na0.x; Ash[c4 * 4 + 1][rs0] = na0.y;
            Ash[c4 * 4 + 2][rs0] = na0.z; Ash[c4 * 4 + 3][rs0] = na0.w;
            Ash[c4 * 4 + 0][rs1] = na1.x; Ash[c4 * 4 + 1][rs1] = na1.y;
            Ash[c4 * 4 + 2][rs1] = na1.z; Ash[c4 * 4 + 3][rs1] = na1.w;
            Bsh[c4 * 4 + 0][rs0] = nb0.x; Bsh[c4 * 4 + 1][rs0] = nb0.y;
            Bsh[c4 * 4 + 2][rs0] = nb0.z; Bsh[c4 * 4 + 3][rs0] = nb0.w;
            Bsh[c4 * 4 + 0][rs1] = nb1.x; Bsh[c4 * 4 + 1][rs1] = nb1.y;
            Bsh[c4 * 4 + 2][rs1] = nb1.z; Bsh[c4 * 4 + 3][rs1] = nb1.w;
            __syncthreads();
        }
    }

    float4 bb = *(const float4*)(bias + col0 + tx * 4);
    #pragma unroll
    for (int i = 0; i < 4; i++) {
        float4 o;
        o.x = acc[i][0] + bb.x; o.y = acc[i][1] + bb.y;
        o.z = acc[i][2] + bb.z; o.w = acc[i][3] + bb.w;
        *(float4*)(C + (size_t)(row0 + ty * 4 + i) * FDIM + col0 + tx * 4) = o;
    }
}

__global__ __launch_bounds__(256, 2)
void qkv_gemm(const float* __restrict__ cur, const float* __restrict__ hist,
              const float* __restrict__ Wq, const float* __restrict__ bq,
              const float* __restrict__ Wk, const float* __restrict__ bk,
              const float* __restrict__ Wv, const float* __restrict__ bv)
{
    const float* A; const float* W; const float* bias; float* C;
    if (blockIdx.z == 0)      { A = cur;  W = Wq; bias = bq; C = g_Q; }
    else if (blockIdx.z == 1) { A = hist; W = Wk; bias = bk; C = g_K; }
    else                      { A = hist; W = Wv; bias = bv; C = g_V; }
    gemm_body(A, W, bias, C);
}

__global__ __launch_bounds__(256, 2)
void out_gemm(const float* __restrict__ Wo, const float* __restrict__ bo,
              float* __restrict__ out)
{
    gemm_body(g_att, Wo, bo, out);
}

// ---------------------------------------------------------------------------
// Masked flash attention over supercell-pure 32-query chunks.
// (exact 180.4us round-14 winner)
// ---------------------------------------------------------------------------
__global__ __launch_bounds__(128, 6)
void attn_kernel(const float* __restrict__ cc, const float* __restrict__ hc)
{
    const int b  = g_border[blockIdx.x];
    const int sc = b / BLKS_PER_SC;
    const int j  = b - sc * BLKS_PER_SC;
    const int base = sc << 6;
    const int qs  = g_qstart[base] + QBLK * j;
    const int cnt = min(QBLK, g_qstart[base + 64] - qs);
    if (cnt <= 0) return;

    __shared__ float Qsh[HD][QBLK];     // [d][query], swizzled
    __shared__ float Ksh[HD][64];       // [d][key], swizzled
    __shared__ float Vsh[64][HD];       // [key][d]
    __shared__ float Ssh[64][QBLK];     // p transposed [key][query], swizzled
    __shared__ float qcx[QBLK], qcy[QBLK], qcz[QBLK];
    __shared__ float kcx[64], kcy[64], kcz[64];
    __shared__ float lsh[QBLK];

    const int tid = threadIdx.x;
    const int h   = blockIdx.y;
    // scores mapping: 8 q-groups x 16 k-groups
    const int ty = tid >> 4, tx = tid & 15;
    // PV mapping: 8 q-groups x 8 d-groups x 2 key-halves
    const int qg = tid & 7, dg = (tid >> 3) & 7, half = tid >> 6;

    // Load Q tile (transposed+swizzled): 32 rows x 8 quads = 256 slots
    #pragma unroll
    for (int i = 0; i < 2; i++) {
        int idx = tid + i * 128;
        int r   = idx >> 3;          // query row 0..31
        int c4  = idx & 7;           // dim quad 0..7
        int qv  = (r < cnt) ? g_qperm[qs + r] : g_qperm[qs];
        float4 v = *(const float4*)(g_Q + (size_t)qv * FDIM + h * HD + c4 * 4);
        int rs = r ^ (c4 * 4);
        Qsh[c4 * 4 + 0][rs] = v.x; Qsh[c4 * 4 + 1][rs] = v.y;
        Qsh[c4 * 4 + 2][rs] = v.z; Qsh[c4 * 4 + 3][rs] = v.w;
    }
    if (tid < QBLK) {
        if (tid < cnt) {
            int qv = g_qperm[qs + tid];
            qcx[tid] = cc[3 * qv]; qcy[tid] = cc[3 * qv + 1]; qcz[tid] = cc[3 * qv + 2];
        } else {
            qcx[tid] = -1e9f; qcy[tid] = -1e9f; qcz[tid] = -1e9f;
        }
    }
    __syncthreads();

    // query coords for this thread's 4 score-rows (block-constant)
    float qx[4], qy[4], qz[4];
    #pragma unroll
    for (int i = 0; i < 4; i++) {
        qx[i] = qcx[ty * 4 + i]; qy[i] = qcy[ty * 4 + i]; qz[i] = qcz[ty * 4 + i];
    }

    const int nc = g_ncand[b];
    const long long boff = (long long)b * NKV;

    float l[4] = {0.f, 0.f, 0.f, 0.f};
    float o[4][4] = {};

    for (int t0 = 0; t0 < nc; t0 += 64) {
        __syncthreads();   // prior PV reads done before overwrite
        // K/V gather: 64 rows x 8 quads = 512 slots over 128 threads
        #pragma unroll
        for (int i = 0; i < 4; i++) {
            int idx = tid + i * 128;
            int r   = idx >> 3;
            int c4  = idx & 7;
            int t   = t0 + r;
            int ci  = (t < nc) ? g_cand[boff + t] : 0;
            float4 kv = *(const float4*)(g_K + (size_t)ci * FDIM + h * HD + c4 * 4);
            int rs = r ^ (c4 * 4);
            Ksh[c4 * 4 + 0][rs] = kv.x; Ksh[c4 * 4 + 1][rs] = kv.y;
            Ksh[c4 * 4 + 2][rs] = kv.z; Ksh[c4 * 4 + 3][rs] = kv.w;
            float4 vv = *(const float4*)(g_V + (size_t)ci * FDIM + h * HD + c4 * 4);
            *(float4*)&Vsh[r][c4 * 4] = vv;
        }
        if (tid < 64) {
            int t = t0 + tid;
            if (t < nc) {
                int ci = g_cand[boff + t];
                kcx[tid] = hc[3 * ci + 0];
                kcy[tid] = hc[3 * ci + 1];
                kcz[tid] = hc[3 * ci + 2];
            } else {
                kcx[tid] = 1e9f; kcy[tid] = 1e9f; kcz[tid] = 1e9f;
            }
        }
        __syncthreads();

        // ---- scores: 4q x 4k microtile ----
        float s[4][4] = {};
        #pragma unroll
        for (int d = 0; d < HD; d++) {
            const int sw = d & 28;
            float4 q4 = *(const float4*)&Qsh[d][(ty * 4) ^ sw];
            float4 k4 = *(const float4*)&Ksh[d][(tx * 4) ^ sw];
            float qa[4] = {q4.x, q4.y, q4.z, q4.w};
            float ka[4] = {k4.x, k4.y, k4.z, k4.w};
            #pragma unroll
            for (int i = 0; i < 4; i++)
                #pragma unroll
                for (int jj = 0; jj < 4; jj++)
                    s[i][jj] += qa[i] * ka[jj];
        }

        float kx[4], ky[4], kz[4];
        #pragma unroll
        for (int jj = 0; jj < 4; jj++) {
            kx[jj] = kcx[tx * 4 + jj]; ky[jj] = kcy[tx * 4 + jj]; kz[jj] = kcz[tx * 4 + jj];
        }

        // ---- mask + exp (static base), accumulate partial l ----
        #pragma unroll
        for (int i = 0; i < 4; i++) {
            #pragma unroll
            for (int jj = 0; jj < 4; jj++) {
                float dx = qx[i] - kx[jj], dy = qy[i] - ky[jj], dz = qz[i] - kz[jj];
                float d2 = dx * dx + dy * dy + dz * dz;
                float p = (d2 <= R2) ? __expf(s[i][jj] * SCALE) : 0.f;
                s[i][jj] = p;
                l[i] += p;
            }
        }

        // store p transposed+swizzled: Ssh[k][(ty ^ ((k>>2)&7))*4 ..]
        #pragma unroll
        for (int jj = 0; jj < 4; jj++) {
            int k = tx * 4 + jj;
            float4 pv = {s[0][jj], s[1][jj], s[2][jj], s[3][jj]};
            *(float4*)&Ssh[k][(ty ^ (tx & 7)) * 4] = pv;
        }
        __syncthreads();

        // ---- PV: 4q x 4d over this thread's 32-key half ----
        const int kbase = half * 32;
        #pragma unroll 8
        for (int kk = 0; kk < 32; kk++) {
            int k = kbase + kk;
            float4 p4 = *(const float4*)&Ssh[k][(qg ^ ((k >> 2) & 7)) * 4];
            float4 v4 = *(const float4*)&Vsh[k][dg * 4];
            o[0][0] += p4.x * v4.x; o[0][1] += p4.x * v4.y; o[0][2] += p4.x * v4.z; o[0][3] += p4.x * v4.w;
            o[1][0] += p4.y * v4.x; o[1][1] += p4.y * v4.y; o[1][2] += p4.y * v4.z; o[1][3] += p4.y * v4.w;
            o[2][0] += p4.z * v4.x; o[2][1] += p4.z * v4.y; o[2][2] += p4.z * v4.z; o[2][3] += p4.z * v4.w;
            o[3][0] += p4.w * v4.x; o[3][1] += p4.w * v4.y; o[3][2] += p4.w * v4.z; o[3][3] += p4.w * v4.w;
        }
    }

    // ---- final l reduction over the 16 tx lanes (once) ----
    #pragma unroll
    for (int i = 0; i < 4; i++) {
        float ls = l[i];
        ls += __shfl_xor_sync(0xffffffffu, ls, 1);
        ls += __shfl_xor_sync(0xffffffffu, ls, 2);
        ls += __shfl_xor_sync(0xffffffffu, ls, 4);
        ls += __shfl_xor_sync(0xffffffffu, ls, 8);
        l[i] = ls;
    }
    if (tx == 0) {
        lsh[ty * 4 + 0] = l[0]; lsh[ty * 4 + 1] = l[1];
        lsh[ty * 4 + 2] = l[2]; lsh[ty * 4 + 3] = l[3];
    }
    __syncthreads();

    // ---- finalize: merge halves, divide by l (l==0 -> NaN like reference) ----
    if (half == 1) {
        #pragma unroll
        for (int i = 0; i < 4; i++) {
            float4 w = {o[i][0], o[i][1], o[i][2], o[i][3]};
            *(float4*)&Ssh[qg * 4 + i][dg * 4] = w;
        }
    }
    __syncthreads();
    if (half == 0) {
        #pragma unroll
        for (int i = 0; i < 4; i++) {
            int qrel = qg * 4 + i;
            if (qrel < cnt) {
                float inv = 1.f / lsh[qrel];
                float4 ot = *(const float4*)&Ssh[qrel][dg * 4];
                int qv = g_qperm[qs + qrel];
                float4 r;
                r.x = (o[i][0] + ot.x) * inv;
                r.y = (o[i][1] + ot.y) * inv;
                r.z = (o[i][2] + ot.z) * inv;
                r.w = (o[i][3] + ot.w) * inv;
                *(float4*)(g_att + (size_t)qv * FDIM + h * HD + dg * 4) = r;
            }
        }
    }
}

// ---------------------------------------------------------------------------
extern "C" void kernel_launch(void* const* d_in, const int* in_sizes, int n_in,
                              void* d_out, int out_size)
{
    const float* cur  = (const float*)d_in[0];
    const float* hist = (const float*)d_in[1];
    const float* cc   = (const float*)d_in[2];
    const float* hc   = (const float*)d_in[3];
    const float* Wq   = (const float*)d_in[4];
    const float* bq   = (const float*)d_in[5];
    const float* Wk   = (const float*)d_in[6];
    const float* bk   = (const float*)d_in[7];
    const float* Wv   = (const float*)d_in[8];
    const float* bv   = (const float*)d_in[9];
    const float* Wo   = (const float*)d_in[10];
    const float* bo   = (const float*)d_in[11];
    float* out = (float*)d_out;

    setup_kernel<<<1, 1024>>>(cc);
    cand_kernel<<<NBLK, 512>>>(cc, hc);
    order_kernel<<<1, NBLK>>>();

    dim3 g1(NQ / 64, FDIM / 64, 3);
    qkv_gemm<<<g1, 256>>>(cur, hist, Wq, bq, Wk, bk, Wv, bv);

    dim3 g2(NBLK, NH);
    attn_kernel<<<g2, 128>>>(cc, hc);

    dim3 g3(NQ / 64, FDIM / 64);
    out_gemm<<<g3, 256>>>(Wo, bo, out);
}